// round 16
// baseline (speedup 1.0000x reference)
#include <cuda_runtime.h>
#include <cstdint>

// Problem constants (fixed shapes from setup_inputs)
#define B_   512
#define C_   100
#define F_   224
#define E_   8192
#define H_   4
#define I_   28
#define INPUTS_ (F_ * I_)          // 6272 == x_b cols, no padding needed
#define FE_  (F_ * E_)             // 1,835,008
#define FE4_ (FE_ / 4)             // 458,752
#define BUILD_BLOCKS (FE4_ / 256)  // 1792
#define XWORDS_ (INPUTS_ / 32)     // 196
#define BHALF_ (B_ / 2)            // 256 batch rows per gather block
#define BWARP_ (BHALF_ / 8)        // 32 batch rows per warp

// Scratch (device globals: allocation-free per harness rules)
// negw[(f*E + e)] : uint4 whose bit c (across 4 words) set <=> table[c][f][e] < 0
__device__ __align__(64) uint32_t g_negw[F_ * E_ * 4];   // 29.36 MB
__device__ int4     g_hashesT[F_ * B_];           // 1.8 MB, [f][b] transposed
__device__ uint4    g_cmask[B_ * F_];             // 1.8 MB, [b][f] OR'd masks

// 32-byte store with L2 evict-last policy (sm_103 requires .v4.b64 width for
// this modifier). Biases L2 toward keeping negw through the table stream.
__device__ __forceinline__ void st32_evict_last(void* p,
                                                uint64_t q0, uint64_t q1,
                                                uint64_t q2, uint64_t q3) {
    asm volatile("st.global.L2::evict_last.v4.b64 [%0], {%1,%2,%3,%4};"
                 :: "l"(p), "l"(q0), "l"(q1), "l"(q2), "l"(q3) : "memory");
}

__device__ __forceinline__ uint64_t pk(uint32_t lo, uint32_t hi) {
    return (uint64_t)lo | ((uint64_t)hi << 32);
}

// ---------------------------------------------------------------------------
// Fused Phase A + B. Blocks [0,BUILD_BLOCKS) stream the 734MB table
// (coalesced float4, evict-first) and pack per-(f,e) 100-bit negative masks
// (stored evict-last, 2x32B per thread). Blocks [BUILD_BLOCKS, +512) compute
// the H3 hashes for one batch row each (stored f-major for the gather phase),
// hiding under the build blocks' DRAM time.
// ---------------------------------------------------------------------------
__global__ void __launch_bounds__(256)
fused_build_hash_kernel(const float* __restrict__ table,
                        const int*   __restrict__ x_b,
                        const int*   __restrict__ input_order,
                        const int*   __restrict__ hash_values)
{
    __shared__ uint32_t s_xbits[XWORDS_];     // 784 B  (packed x row)
    __shared__ int      s_hv[H_ * I_];        // 448 B

    const int bid = blockIdx.x;

    if (bid < BUILD_BLOCKS) {
        // ---------------- build role ----------------
        const int t = bid * 256 + threadIdx.x;            // 0 .. FE4_-1
        const float4* p = reinterpret_cast<const float4*>(table) + t;

        uint32_t a0[4] = {0,0,0,0};
        uint32_t a1[4] = {0,0,0,0};
        uint32_t a2[4] = {0,0,0,0};
        uint32_t a3[4] = {0,0,0,0};

        #pragma unroll
        for (int c = 0; c < C_; ++c) {
            float4 v = __ldcs(p + (size_t)c * FE4_);
            const uint32_t bit = 1u << (c & 31);
            const int w = c >> 5;                         // compile-time
            if (v.x < 0.0f) a0[w] |= bit;
            if (v.y < 0.0f) a1[w] |= bit;
            if (v.z < 0.0f) a2[w] |= bit;
            if (v.w < 0.0f) a3[w] |= bit;
        }

        char* o = reinterpret_cast<char*>(g_negw) + (size_t)t * 64;
        st32_evict_last(o,
                        pk(a0[0], a0[1]), pk(a0[2], a0[3]),
                        pk(a1[0], a1[1]), pk(a1[2], a1[3]));
        st32_evict_last(o + 32,
                        pk(a2[0], a2[1]), pk(a2[2], a2[3]),
                        pk(a3[0], a3[1]), pk(a3[2], a3[3]));
    } else {
        // ---------------- hash role ----------------
        const int b    = bid - BUILD_BLOCKS;
        const int tid  = threadIdx.x;
        const int wid  = tid >> 5;
        const int lane = tid & 31;

        // Ballot-pack the 6272-bit x row into 196 smem words.
        const int* xr = x_b + (size_t)b * INPUTS_;
        for (int j = wid; j < XWORDS_; j += 8) {
            int v = xr[j * 32 + lane];
            uint32_t bal = __ballot_sync(0xFFFFFFFFu, v != 0);
            if (lane == 0) s_xbits[j] = bal;
        }
        if (tid < H_ * I_)
            s_hv[tid] = hash_values[tid];
        __syncthreads();

        const int f = tid;
        if (f < F_) {
            const int* ord = input_order + f * I_;
            int h0 = 0, h1 = 0, h2 = 0, h3 = 0;
            #pragma unroll
            for (int i = 0; i < I_; ++i) {
                const int idx = __ldg(&ord[i]);
                const int m = -(int)((s_xbits[idx >> 5] >> (idx & 31)) & 1u);
                h0 ^= s_hv[0 * I_ + i] & m;
                h1 ^= s_hv[1 * I_ + i] & m;
                h2 ^= s_hv[2 * I_ + i] & m;
                h3 ^= s_hv[3 * I_ + i] & m;
            }
            g_hashesT[f * B_ + b] = make_int4(h0, h1, h2, h3);
        }
    }
}

// ---------------------------------------------------------------------------
// Phase C1: gather. Block = (filter f, b-half); the block's negw slice
// (~113KB of touched lines) becomes L1-resident, so the 4 warp-uniform uint4
// loads per batch row are L1 hits after first touch. The OR'd 128-bit mask
// per (b,f) is stored dense to g_cmask[b][f] for the reduce pass.
// ---------------------------------------------------------------------------
__global__ void __launch_bounds__(256)
gather_kernel()
{
    __shared__ int4 s_h[BHALF_];         // 4 KB staged hashes

    const int f    = blockIdx.x;
    const int b0   = blockIdx.y * BHALF_;
    const int tid  = threadIdx.x;
    const int wi   = tid >> 5;
    const int lane = tid & 31;

    // Stage this block's hashes: 256 int4 = 1024 ints, coalesced.
    const int* hsrc = reinterpret_cast<const int*>(g_hashesT + f * B_ + b0);
    #pragma unroll
    for (int j = 0; j < 4; ++j)
        reinterpret_cast<int*>(s_h)[tid + j * 256] = __ldg(&hsrc[tid + j * 256]);
    __syncthreads();

    const uint4* base = reinterpret_cast<const uint4*>(g_negw) + (size_t)f * E_;

    #pragma unroll 1
    for (int k = 0; k < BWARP_; k += 4) {
        uint4 m[4];
        #pragma unroll
        for (int u = 0; u < 4; ++u) {
            const int bb = wi * BWARP_ + k + u;
            const int4 h = s_h[bb];
            const uint4 ma = __ldg(&base[h.x]);
            const uint4 mb = __ldg(&base[h.y]);
            const uint4 mc = __ldg(&base[h.z]);
            const uint4 md = __ldg(&base[h.w]);
            m[u] = make_uint4(ma.x | mb.x | mc.x | md.x,
                              ma.y | mb.y | mc.y | md.y,
                              ma.z | mb.z | mc.z | md.z,
                              ma.w | mb.w | mc.w | md.w);
        }
        if (lane == 0) {
            #pragma unroll
            for (int u = 0; u < 4; ++u) {
                const int bb = wi * BWARP_ + k + u;
                g_cmask[(size_t)(b0 + bb) * F_ + f] = m[u];
            }
        }
    }
}

// ---------------------------------------------------------------------------
// Phase C2: reduce. Block = batch row b; stage the row's 224 masks (3.5KB)
// coalesced into smem, then thread c counts its bit over all filters.
// out[b][c] = bias[c] + F - 2 * count
// ---------------------------------------------------------------------------
__global__ void __launch_bounds__(128)
reduce_kernel(const float* __restrict__ bias, float* __restrict__ out)
{
    __shared__ uint32_t s_raw[F_ * 4];   // 3.5 KB

    const int b   = blockIdx.x;
    const int tid = threadIdx.x;

    const uint32_t* src = reinterpret_cast<const uint32_t*>(g_cmask + (size_t)b * F_);
    #pragma unroll
    for (int j = 0; j < 7; ++j)
        s_raw[tid + j * 128] = __ldg(&src[tid + j * 128]);
    __syncthreads();

    const int w  = tid >> 5;             // mask word for class tid
    const int sh = tid & 31;

    int cnt = 0;
    #pragma unroll 8
    for (int f = 0; f < F_; ++f)
        cnt += (s_raw[f * 4 + w] >> sh) & 1;

    if (tid < C_)
        out[b * C_ + tid] = bias[tid] + (float)(F_ - 2 * cnt);
}

// ---------------------------------------------------------------------------
// Launch. Input order per metadata: x_b, input_order, hash_values, table, bias
// ---------------------------------------------------------------------------
extern "C" void kernel_launch(void* const* d_in, const int* in_sizes, int n_in,
                              void* d_out, int out_size)
{
    const int*   x_b         = (const int*)  d_in[0];
    const int*   input_order = (const int*)  d_in[1];
    const int*   hash_values = (const int*)  d_in[2];
    const float* table       = (const float*)d_in[3];
    const float* bias        = (const float*)d_in[4];
    float*       out         = (float*)d_out;

    // Phase A+B fused: table stream + sign-mask build, hash blocks in the tail
    fused_build_hash_kernel<<<BUILD_BLOCKS + B_, 256>>>(
        table, x_b, input_order, hash_values);

    // Phase C1: filter-major gather (L1-resident negw slice per block)
    gather_kernel<<<dim3(F_, B_ / BHALF_), 256>>>();

    // Phase C2: per-row bit reduce + bias
    reduce_kernel<<<B_, 128>>>(bias, out);
}

// round 17
// speedup vs baseline: 1.0521x; 1.0521x over previous
#include <cuda_runtime.h>
#include <cstdint>

// Problem constants (fixed shapes from setup_inputs)
#define B_   512
#define C_   100
#define F_   224
#define E_   8192
#define H_   4
#define I_   28
#define INPUTS_ (F_ * I_)          // 6272 == x_b cols, no padding needed
#define FE_  (F_ * E_)             // 1,835,008
#define FE4_ (FE_ / 4)             // 458,752
#define BUILD_BLOCKS (FE4_ / 256)  // 1792
#define XWORDS_ (INPUTS_ / 32)     // 196
#define NSEG_ 14                   // accum f-segments
#define FSEG_ (F_ / NSEG_)         // 16 filters per segment
#define FWARP_ (FSEG_ / 8)         // 2 filters per warp

// Scratch (device globals: allocation-free per harness rules)
// negw[(f*E + e)] : uint4 whose bit c (across 4 words) set <=> table[c][f][e] < 0
__device__ __align__(64) uint32_t g_negw[F_ * E_ * 4];   // 29.36 MB
__device__ int4     g_hashes[B_ * F_];            // 1.8 MB

// 32-byte store with L2 evict-last policy (sm_103 requires .v4.b64 width for
// this modifier). Biases L2 toward keeping negw through the table stream.
__device__ __forceinline__ void st32_evict_last(void* p,
                                                uint64_t q0, uint64_t q1,
                                                uint64_t q2, uint64_t q3) {
    asm volatile("st.global.L2::evict_last.v4.b64 [%0], {%1,%2,%3,%4};"
                 :: "l"(p), "l"(q0), "l"(q1), "l"(q2), "l"(q3) : "memory");
}

__device__ __forceinline__ uint64_t pk(uint32_t lo, uint32_t hi) {
    return (uint64_t)lo | ((uint64_t)hi << 32);
}

// ---------------------------------------------------------------------------
// Fused Phase A + B. Blocks [0,BUILD_BLOCKS) stream the 734MB table
// (coalesced float4, evict-first) and pack per-(f,e) 100-bit negative masks
// (stored evict-last, 2x32B per thread). Blocks [BUILD_BLOCKS, +512) compute
// the H3 hashes for one batch row each AND initialize out[b][:] = bias + F,
// all hiding under the build blocks' DRAM time.
// ---------------------------------------------------------------------------
__global__ void __launch_bounds__(256)
fused_build_hash_kernel(const float* __restrict__ table,
                        const int*   __restrict__ x_b,
                        const int*   __restrict__ input_order,
                        const int*   __restrict__ hash_values,
                        const float* __restrict__ bias,
                        float*       __restrict__ out)
{
    __shared__ uint32_t s_xbits[XWORDS_];     // 784 B  (packed x row)
    __shared__ int      s_hv[H_ * I_];        // 448 B

    const int bid = blockIdx.x;

    if (bid < BUILD_BLOCKS) {
        // ---------------- build role ----------------
        const int t = bid * 256 + threadIdx.x;            // 0 .. FE4_-1
        const float4* p = reinterpret_cast<const float4*>(table) + t;

        uint32_t a0[4] = {0,0,0,0};
        uint32_t a1[4] = {0,0,0,0};
        uint32_t a2[4] = {0,0,0,0};
        uint32_t a3[4] = {0,0,0,0};

        #pragma unroll
        for (int c = 0; c < C_; ++c) {
            float4 v = __ldcs(p + (size_t)c * FE4_);
            const uint32_t bit = 1u << (c & 31);
            const int w = c >> 5;                         // compile-time
            if (v.x < 0.0f) a0[w] |= bit;
            if (v.y < 0.0f) a1[w] |= bit;
            if (v.z < 0.0f) a2[w] |= bit;
            if (v.w < 0.0f) a3[w] |= bit;
        }

        char* o = reinterpret_cast<char*>(g_negw) + (size_t)t * 64;
        st32_evict_last(o,
                        pk(a0[0], a0[1]), pk(a0[2], a0[3]),
                        pk(a1[0], a1[1]), pk(a1[2], a1[3]));
        st32_evict_last(o + 32,
                        pk(a2[0], a2[1]), pk(a2[2], a2[3]),
                        pk(a3[0], a3[1]), pk(a3[2], a3[3]));
    } else {
        // ---------------- hash + out-init role ----------------
        const int b    = bid - BUILD_BLOCKS;
        const int tid  = threadIdx.x;
        const int wid  = tid >> 5;
        const int lane = tid & 31;

        // Initialize out[b][:] = bias + F (accum blocks atomically subtract).
        if (tid < C_)
            out[b * C_ + tid] = bias[tid] + (float)F_;

        // Ballot-pack the 6272-bit x row into 196 smem words.
        const int* xr = x_b + (size_t)b * INPUTS_;
        for (int j = wid; j < XWORDS_; j += 8) {
            int v = xr[j * 32 + lane];
            uint32_t bal = __ballot_sync(0xFFFFFFFFu, v != 0);
            if (lane == 0) s_xbits[j] = bal;
        }
        if (tid < H_ * I_)
            s_hv[tid] = hash_values[tid];
        __syncthreads();

        const int f = tid;
        if (f < F_) {
            const int* ord = input_order + f * I_;
            int h0 = 0, h1 = 0, h2 = 0, h3 = 0;
            #pragma unroll
            for (int i = 0; i < I_; ++i) {
                const int idx = __ldg(&ord[i]);
                const int m = -(int)((s_xbits[idx >> 5] >> (idx & 31)) & 1u);
                h0 ^= s_hv[0 * I_ + i] & m;
                h1 ^= s_hv[1 * I_ + i] & m;
                h2 ^= s_hv[2 * I_ + i] & m;
                h3 ^= s_hv[3 * I_ + i] & m;
            }
            g_hashes[b * F_ + f] = make_int4(h0, h1, h2, h3);
        }
    }
}

// ---------------------------------------------------------------------------
// Phase C: accumulate. Block = (batch row b, f-segment seg); 8 warps x 2
// filters each (7168 blocks -> 57k independent warps; each warp issues all 8
// warp-uniform uint4 loads back-to-back -> one scoreboard wait per warp).
// Block partials are subtracted from out via atomicAdd of exact
// integer-valued floats (order-independent, deterministic).
// out[b][c] = bias[c] + F - 2 * #{ f : OR_h negmask(f, hash_h) has bit c }
// ---------------------------------------------------------------------------
__global__ void __launch_bounds__(256, 8)
accum_kernel(float* __restrict__ out)
{
    __shared__ int4 s_h[FSEG_];          // 16 staged hashes
    __shared__ int  s_cnt[8 * 132];

    const int b    = blockIdx.x;
    const int seg  = blockIdx.y;
    const int tid  = threadIdx.x;
    const int wi   = tid >> 5;
    const int lane = tid & 31;

    // Stage this block's hashes: 16 int4 = 64 ints, coalesced.
    const int* hsrc = reinterpret_cast<const int*>(g_hashes + b * F_ + seg * FSEG_);
    if (tid < FSEG_ * 4)
        reinterpret_cast<int*>(s_h)[tid] = __ldg(&hsrc[tid]);
    __syncthreads();

    const uint4* nw = reinterpret_cast<const uint4*>(g_negw);
    const int fbase = seg * FSEG_ + wi * FWARP_;

    // Issue all 8 loads before any consumption.
    uint4 m[FWARP_][4];
    #pragma unroll
    for (int k = 0; k < FWARP_; ++k) {
        const int4 h = s_h[wi * FWARP_ + k];
        const uint4* base = nw + (size_t)(fbase + k) * E_;
        m[k][0] = __ldg(&base[h.x]);
        m[k][1] = __ldg(&base[h.y]);
        m[k][2] = __ldg(&base[h.z]);
        m[k][3] = __ldg(&base[h.w]);
    }

    int c0 = 0, c1 = 0, c2 = 0, c3 = 0;
    #pragma unroll
    for (int k = 0; k < FWARP_; ++k) {
        const uint32_t mx = m[k][0].x | m[k][1].x | m[k][2].x | m[k][3].x;
        const uint32_t my = m[k][0].y | m[k][1].y | m[k][2].y | m[k][3].y;
        const uint32_t mz = m[k][0].z | m[k][1].z | m[k][2].z | m[k][3].z;
        const uint32_t mw = m[k][0].w | m[k][1].w | m[k][2].w | m[k][3].w;
        c0 += (mx >> lane) & 1;
        c1 += (my >> lane) & 1;
        c2 += (mz >> lane) & 1;
        c3 += (mw >> lane) & 1;
    }

    int* sr = s_cnt + wi * 132;
    sr[lane]      = c0;
    sr[lane + 32] = c1;
    sr[lane + 64] = c2;
    sr[lane + 96] = c3;
    __syncthreads();

    if (tid < C_) {
        int total = 0;
        #pragma unroll
        for (int w = 0; w < 8; ++w)
            total += s_cnt[w * 132 + tid];
        atomicAdd(&out[b * C_ + tid], (float)(-2 * total));
    }
}

// ---------------------------------------------------------------------------
// Launch. Input order per metadata: x_b, input_order, hash_values, table, bias
// ---------------------------------------------------------------------------
extern "C" void kernel_launch(void* const* d_in, const int* in_sizes, int n_in,
                              void* d_out, int out_size)
{
    const int*   x_b         = (const int*)  d_in[0];
    const int*   input_order = (const int*)  d_in[1];
    const int*   hash_values = (const int*)  d_in[2];
    const float* table       = (const float*)d_in[3];
    const float* bias        = (const float*)d_in[4];
    float*       out         = (float*)d_out;

    // Phase A+B fused: table stream + sign-mask build; hash blocks (which
    // also init out = bias + F) ride in the tail of the grid.
    fused_build_hash_kernel<<<BUILD_BLOCKS + B_, 256>>>(
        table, x_b, input_order, hash_values, bias, out);

    // Phase C: gather+accumulate, atomically folding partials into out
    accum_kernel<<<dim3(B_, NSEG_), 256>>>(out);
}